// round 4
// baseline (speedup 1.0000x reference)
#include <cuda_runtime.h>
#include <math.h>

#define VOCAB  32000
#define EMBED  512
#define HIDDEN 1024
#define OUTN   32000
#define BATCH  64
#define TLEN   512
#define CDIM   (EMBED + HIDDEN)   /* 1536 */
#define NSTEP  (TLEN - 1)         /* 511  */
#define NCTA   128

// ---------------- scratch: __device__ globals (allocation-free) ----------------
__device__ __align__(128) float g_tab[(size_t)VOCAB * EMBED];             // (V,E) table, bias folded
__device__ __align__(128) float g_emb[(size_t)TLEN * BATCH * EMBED];      // [t][b][e]
__device__ __align__(128) float g_U[(size_t)NSTEP * BATCH * HIDDEN];      // [t][b][j]
__device__ __align__(128) float g_Z[3][BATCH * HIDDEN];                   // h rotation buffers
__device__ __align__(128) float g_comb[BATCH * CDIM];
__device__ unsigned g_bar;

// ---------------- transpose i2e_w (E,V) -> (V,E), fold bias ----------------
__global__ void k_transpose(const float* __restrict__ W, const float* __restrict__ bias) {
    __shared__ float tile[32][33];
    int v0 = blockIdx.x * 32, e0 = blockIdx.y * 32;
    int tx = threadIdx.x, ty = threadIdx.y;
#pragma unroll
    for (int i = 0; i < 32; i += 8)
        tile[ty + i][tx] = W[(size_t)(e0 + ty + i) * VOCAB + v0 + tx];
    __syncthreads();
    float bv = bias[e0 + tx];
#pragma unroll
    for (int i = 0; i < 32; i += 8)
        g_tab[(size_t)(v0 + ty + i) * EMBED + e0 + tx] = tile[tx][ty + i] + bv;
}

// ---------------- embedding gather: g_emb[t][b][:] = g_tab[tok][:] ----------------
__global__ void k_gather(const int* __restrict__ tokens) {
    int bid = blockIdx.x;                  // bid = t*64 + b
    int t = bid >> 6, b = bid & 63;
    int tok = tokens[b * TLEN + t];
    const float4* src = (const float4*)(g_tab + (size_t)tok * EMBED);
    float4* dst = (float4*)(g_emb + (size_t)bid * EMBED);
    dst[threadIdx.x] = src[threadIdx.x];   // 128 thr x float4 = 512 floats
}

// ---------------- NT GEMM: C[M,N] = A[M,K] * B[N,K]^T + bias[N] ----------------
// BM=64 BN=128 BK=16, 256 threads, 4x8 per-thread tile. All dims divide exactly.
// mode 0: A=g_emb (lda=512, K=512), C=g_U (ldc=1024)        [U projection]
// mode 1: A=g_comb (lda=1536, K=1536), C=Cext (ldc=32000)   [logits]
__global__ void __launch_bounds__(256) k_gemm(int mode, const float* __restrict__ Bw,
                                              const float* __restrict__ bias,
                                              float* __restrict__ Cext) {
    const float* A; float* C; int lda, ldc, K;
    if (mode == 0) { A = g_emb;  C = g_U;  lda = EMBED; ldc = HIDDEN; K = EMBED; }
    else           { A = g_comb; C = Cext; lda = CDIM;  ldc = OUTN;   K = CDIM;  }
    const int ldb = CDIM;

    __shared__ float As[16][68];
    __shared__ float Bs[16][132];
    const int m0 = blockIdx.y * 64, n0 = blockIdx.x * 128;
    const int tid = threadIdx.x;
    const int a_m = tid >> 2, a_k = (tid & 3) * 4;
    const int b_n = tid >> 1, b_k = (tid & 1) * 8;
    const int ty = tid >> 4, tx = tid & 15;
    float acc[4][8];
#pragma unroll
    for (int i = 0; i < 4; i++)
#pragma unroll
        for (int j = 0; j < 8; j++) acc[i][j] = 0.f;

    const float* Ag = A + (size_t)(m0 + a_m) * lda + a_k;
    const float* Bg = Bw + (size_t)(n0 + b_n) * ldb + b_k;

    for (int k0 = 0; k0 < K; k0 += 16) {
        float4 av  = *(const float4*)(Ag + k0);
        float4 bv0 = *(const float4*)(Bg + k0);
        float4 bv1 = *(const float4*)(Bg + k0 + 4);
        As[a_k + 0][a_m] = av.x;  As[a_k + 1][a_m] = av.y;
        As[a_k + 2][a_m] = av.z;  As[a_k + 3][a_m] = av.w;
        Bs[b_k + 0][b_n] = bv0.x; Bs[b_k + 1][b_n] = bv0.y;
        Bs[b_k + 2][b_n] = bv0.z; Bs[b_k + 3][b_n] = bv0.w;
        Bs[b_k + 4][b_n] = bv1.x; Bs[b_k + 5][b_n] = bv1.y;
        Bs[b_k + 6][b_n] = bv1.z; Bs[b_k + 7][b_n] = bv1.w;
        __syncthreads();
#pragma unroll
        for (int kk = 0; kk < 16; ++kk) {
            float4 a4  = *(const float4*)&As[kk][ty * 4];
            float4 b4l = *(const float4*)&Bs[kk][tx * 8];
            float4 b4h = *(const float4*)&Bs[kk][tx * 8 + 4];
            float a[4] = {a4.x, a4.y, a4.z, a4.w};
            float b[8] = {b4l.x, b4l.y, b4l.z, b4l.w, b4h.x, b4h.y, b4h.z, b4h.w};
#pragma unroll
            for (int i = 0; i < 4; i++)
#pragma unroll
                for (int j = 0; j < 8; j++) acc[i][j] += a[i] * b[j];
        }
        __syncthreads();
    }
#pragma unroll
    for (int i = 0; i < 4; i++) {
        int m = m0 + ty * 4 + i;
#pragma unroll
        for (int jq = 0; jq < 2; jq++) {
            int n = n0 + tx * 8 + jq * 4;
            float4 r;
            r.x = acc[i][jq * 4 + 0] + bias[n + 0];
            r.y = acc[i][jq * 4 + 1] + bias[n + 1];
            r.z = acc[i][jq * 4 + 2] + bias[n + 2];
            r.w = acc[i][jq * 4 + 3] + bias[n + 3];
            *(float4*)(C + (size_t)m * ldc + n) = r;
        }
    }
}

// ---------------- scan init: Z[0]=h0=0, Z[1]=U[0], bar=0 ----------------
__global__ void k_zinit() {
    int idx = blockIdx.x * blockDim.x + threadIdx.x;
    if (idx < BATCH * HIDDEN) {
        g_Z[0][idx] = 0.f;
        g_Z[1][idx] = g_U[idx];
        g_Z[2][idx] = 0.f;
    }
    if (idx == 0) g_bar = 0u;
}

// ---------------- persistent RNN scan ----------------
// 128 CTAs = 16 j-groups (64 wide) x 8 k-groups (128 wide). Per step:
// partial (64b x 64j over 128k) in regs -> REDG into pre-initialized buffer,
// stage U[t+1] into the 3rd buffer, one grid barrier.
__global__ void __launch_bounds__(256) k_scan(const float* __restrict__ i2h_w) {
    extern __shared__ float smem_dyn[];
    float* ws = smem_dyn;          // [64 j][128 k], XOR-swizzled float4 columns
    float* hs = smem_dyn + 8192;   // [64 b][128 k], same swizzle
    const int tid = threadIdx.x, bid = blockIdx.x;
    const int jg = bid >> 3, kg = bid & 7;
    const int j0 = jg << 6, k0 = kg << 7;
    const int tx = tid & 15, ty = tid >> 4;
    const int b0 = tx << 2, jl0 = ty << 2;

    // load Wh_h slice once: ws[j][k] = i2h_w[j0+j][EMBED + k0+k]
    for (int q = tid; q < 2048; q += 256) {
        int j = q >> 5, c4 = q & 31;
        float4 v = *(const float4*)(i2h_w + (size_t)(j0 + j) * CDIM + EMBED + k0 + (c4 << 2));
        *(float4*)(ws + j * 128 + (((c4 ^ (j & 31)) << 2))) = v;
    }

    unsigned target = 0;
    for (int t = 0; t < NSTEP; ++t) {
        const float* Zr = g_Z[t % 3];
        float*       Zn = g_Z[(t + 1) % 3];
        float*       Zp = g_Z[(t + 2) % 3];

        // load h slice: hs[b][k] = Zr[b][k0+k]  (L2-only: producers were REDG/STG)
        for (int q = tid; q < 2048; q += 256) {
            int b = q >> 5, c4 = q & 31;
            float4 v = __ldcg((const float4*)(Zr + b * HIDDEN + k0 + (c4 << 2)));
            *(float4*)(hs + b * 128 + (((c4 ^ (b & 31)) << 2))) = v;
        }
        __syncthreads();

        float acc[4][4];
#pragma unroll
        for (int i = 0; i < 4; i++)
#pragma unroll
            for (int j = 0; j < 4; j++) acc[i][j] = 0.f;

#pragma unroll 4
        for (int c4 = 0; c4 < 32; ++c4) {
            float4 a[4], w[4];
#pragma unroll
            for (int i = 0; i < 4; i++)
                a[i] = *(const float4*)(hs + (b0 + i) * 128 + (((c4 ^ ((b0 + i) & 31)) << 2)));
#pragma unroll
            for (int j = 0; j < 4; j++)
                w[j] = *(const float4*)(ws + (jl0 + j) * 128 + (((c4 ^ ((jl0 + j) & 31)) << 2)));
#pragma unroll
            for (int i = 0; i < 4; i++)
#pragma unroll
                for (int j = 0; j < 4; j++)
                    acc[i][j] += a[i].x * w[j].x + a[i].y * w[j].y
                               + a[i].z * w[j].z + a[i].w * w[j].w;
        }

        // accumulate partials into Zn (pre-filled with U[t])
#pragma unroll
        for (int i = 0; i < 4; i++)
#pragma unroll
            for (int j = 0; j < 4; j++)
                atomicAdd(Zn + (b0 + i) * HIDDEN + j0 + jl0 + j, acc[i][j]);

        // stage next input: Zp = U[t+1] (this CTA's 512-float slice)
        if (t < NSTEP - 1) {
            const float2 v = *(const float2*)(g_U + (size_t)(t + 1) * (BATCH * HIDDEN)
                                              + bid * 512 + tid * 2);
            *(float2*)(Zp + bid * 512 + tid * 2) = v;
        }

        // one grid barrier per step (monotonic counter)
        target += NCTA;
        __threadfence();
        __syncthreads();
        if (tid == 0) {
            atomicAdd(&g_bar, 1u);
            while (*((volatile unsigned*)&g_bar) < target) __nanosleep(64);
        }
        __syncthreads();
        __threadfence();
    }
}

// ---------------- combined = concat(emb[:, -1], h_last=Z[1]) ----------------
__global__ void k_combined() {
    int idx = blockIdx.x * blockDim.x + threadIdx.x;   // 96*1024 = 98304
    if (idx >= BATCH * CDIM) return;
    int b = idx / CDIM, c = idx - b * CDIM;
    float v;
    if (c < EMBED) v = g_emb[(size_t)(NSTEP * BATCH + b) * EMBED + c];  // t = 511
    else           v = g_Z[1][b * HIDDEN + (c - EMBED)];
    g_comb[idx] = v;
}

// ---------------- in-place softmax over rows of d_out ----------------
__device__ __forceinline__ float blk_reduce(float v, bool is_max) {
    __shared__ float red[32];
    int lane = threadIdx.x & 31, wid = threadIdx.x >> 5;
#pragma unroll
    for (int o = 16; o > 0; o >>= 1) {
        float u = __shfl_xor_sync(0xffffffffu, v, o);
        v = is_max ? fmaxf(v, u) : (v + u);
    }
    if (lane == 0) red[wid] = v;
    __syncthreads();
    v = (lane < 32) ? red[lane] : (is_max ? -3.0e38f : 0.f);
    if (wid == 0) {
#pragma unroll
        for (int o = 16; o > 0; o >>= 1) {
            float u = __shfl_xor_sync(0xffffffffu, v, o);
            v = is_max ? fmaxf(v, u) : (v + u);
        }
        if (lane == 0) red[0] = v;
    }
    __syncthreads();
    v = red[0];
    __syncthreads();
    return v;
}

__global__ void __launch_bounds__(1024) k_softmax(float* __restrict__ out) {
    float* row = out + (size_t)blockIdx.x * OUTN;
    int tid = threadIdx.x;
    float mx = -3.0e38f;
    for (int i = tid; i < OUTN; i += 1024) mx = fmaxf(mx, row[i]);
    mx = blk_reduce(mx, true);
    float s = 0.f;
    for (int i = tid; i < OUTN; i += 1024) {
        float e = expf(row[i] - mx);
        row[i] = e;
        s += e;
    }
    s = blk_reduce(s, false);
    float inv = 1.0f / s;
    for (int i = tid; i < OUTN; i += 1024) row[i] *= inv;
}

// ---------------- launch ----------------
extern "C" void kernel_launch(void* const* d_in, const int* in_sizes, int n_in,
                              void* d_out, int out_size) {
    const int*   tokens = (const int*)  d_in[0];
    const float* i2e_w  = (const float*)d_in[1];
    const float* i2e_b  = (const float*)d_in[2];
    const float* i2o_w  = (const float*)d_in[3];
    const float* i2o_b  = (const float*)d_in[4];
    const float* i2h_w  = (const float*)d_in[5];
    const float* i2h_b  = (const float*)d_in[6];
    float* out = (float*)d_out;

    cudaFuncSetAttribute(k_scan, cudaFuncAttributeMaxDynamicSharedMemorySize, 65536);

    k_transpose<<<dim3(VOCAB / 32, EMBED / 32), dim3(32, 8)>>>(i2e_w, i2e_b);
    k_gather<<<TLEN * BATCH, 128>>>(tokens);
    k_gemm<<<dim3(HIDDEN / 128, (NSTEP * BATCH) / 64), 256>>>(0, i2h_w, i2h_b, nullptr);
    k_zinit<<<64, 1024>>>();
    k_scan<<<NCTA, 256, 65536>>>(i2h_w);
    k_combined<<<96, 1024>>>();
    k_gemm<<<dim3(OUTN / 128, 1), 256>>>(1, i2o_w, i2o_b, out);
    k_softmax<<<BATCH, 1024>>>(out);
}

// round 5
// speedup vs baseline: 1.0755x; 1.0755x over previous
#include <cuda_runtime.h>
#include <math.h>

#define VOCAB  32000
#define EMBED  512
#define HIDDEN 1024
#define OUTN   32000
#define BATCH  64
#define TLEN   512
#define CDIM   (EMBED + HIDDEN)   /* 1536 */
#define NSTEP  (TLEN - 1)         /* 511  */
#define NHALF  255                /* doubled steps: 1 + 2*255 = 511 */
#define NCTA   128

// ---------------- scratch: __device__ globals (allocation-free) ----------------
__device__ __align__(128) float g_tab[(size_t)VOCAB * EMBED];
__device__ __align__(128) float g_emb[(size_t)TLEN * BATCH * EMBED];       // [t][b][e]
__device__ __align__(128) float g_U[(size_t)NSTEP * BATCH * HIDDEN];       // [t][b][j]
__device__ __align__(128) float g_V[(size_t)NHALF * BATCH * HIDDEN];       // [s][b][j]
__device__ __align__(128) float g_Wt[(size_t)HIDDEN * HIDDEN];             // Wt[a][b]=W[b][a]
__device__ __align__(128) float g_W2t[(size_t)HIDDEN * HIDDEN];            // W2t[k][j]=W2[j][k]
__device__ __align__(128) float g_Z[3][BATCH * HIDDEN];
__device__ __align__(128) float g_comb[BATCH * CDIM];
__device__ unsigned g_bar;

// ---------------- packed f32x2 helpers ----------------
__device__ __forceinline__ unsigned long long pk2(float x) {
    unsigned long long d;
    asm("mov.b64 %0, {%1, %1};" : "=l"(d) : "f"(x));
    return d;
}
__device__ __forceinline__ float2 upk(unsigned long long v) {
    float2 r;
    asm("mov.b64 {%0, %1}, %2;" : "=f"(r.x), "=f"(r.y) : "l"(v));
    return r;
}
#define FMA2(d, a, b) asm("fma.rn.f32x2 %0, %1, %2, %0;" : "+l"(d) : "l"(a), "l"(b))

// ---------------- transpose i2e_w (E,V) -> (V,E), fold bias ----------------
__global__ void k_transpose(const float* __restrict__ W, const float* __restrict__ bias) {
    __shared__ float tile[32][33];
    int v0 = blockIdx.x * 32, e0 = blockIdx.y * 32;
    int tx = threadIdx.x, ty = threadIdx.y;
#pragma unroll
    for (int i = 0; i < 32; i += 8)
        tile[ty + i][tx] = W[(size_t)(e0 + ty + i) * VOCAB + v0 + tx];
    __syncthreads();
    float bv = bias[e0 + tx];
#pragma unroll
    for (int i = 0; i < 32; i += 8)
        g_tab[(size_t)(v0 + ty + i) * EMBED + e0 + tx] = tile[tx][ty + i] + bv;
}

// ---------------- transpose Wh_h: g_Wt[a][b] = W[b][a] ----------------
__global__ void k_transposeW(const float* __restrict__ i2h_w) {
    __shared__ float tile[32][33];
    int b0 = blockIdx.x * 32, a0 = blockIdx.y * 32;
    int tx = threadIdx.x, ty = threadIdx.y;
#pragma unroll
    for (int i = 0; i < 32; i += 8)
        tile[ty + i][tx] = i2h_w[(size_t)(b0 + ty + i) * CDIM + EMBED + a0 + tx];
    __syncthreads();
#pragma unroll
    for (int i = 0; i < 32; i += 8)
        g_Wt[(size_t)(a0 + ty + i) * HIDDEN + b0 + tx] = tile[tx][ty + i];
}

// ---------------- embedding gather ----------------
__global__ void k_gather(const int* __restrict__ tokens) {
    int bid = blockIdx.x;                  // bid = t*64 + b
    int t = bid >> 6, b = bid & 63;
    int tok = tokens[b * TLEN + t];
    const float4* src = (const float4*)(g_tab + (size_t)tok * EMBED);
    float4* dst = (float4*)(g_emb + (size_t)bid * EMBED);
    dst[threadIdx.x] = src[threadIdx.x];
}

// ---------------- unified NT GEMM with f32x2: C[64m x 64n] per CTA ----------------
// 256 thr = 8 warps; warp -> 8 n; lane -> m = {l, l+32}. acc = 2m x 4 j-pairs.
// ldb is always CDIM (all B matrices are rows of i2h_w / i2o_w).
// mode 0: U   = emb(t) @ Wh_e^T + i2h_b          A=g_emb[by], C=g_U[by]
// mode 1: out = comb @ i2o_w^T + i2o_b           A=g_comb,    C=Cext (ldc 32000)
// mode 2: W2t = Wt @ W^T  (i.e. W2 transposed)   A=g_Wt[by],  C=g_W2t[by]
// mode 3: V_s = U[2s+1] @ W^T + U[2s+2]          A=g_U[2by+1],C=g_V[by], add U[2by+2]
__global__ void __launch_bounds__(256) k_gemm2(int mode, const float* __restrict__ Bw,
                                               const float* __restrict__ biasp,
                                               float* __restrict__ Cext) {
    __shared__ float As[32 * 69];   // As[k][m], m contiguous
    __shared__ float Bs[32 * 68];   // Bs[k][n], n contiguous (broadcast reads)
    const int bx = blockIdx.x, by = blockIdx.y;
    const int tid = threadIdx.x;
    const int w = tid >> 5, l = tid & 31;
    const int n0 = bx << 6;

    const float* Abase; float* Cbase; const float* addbase = nullptr;
    int lda, ldc, K;
    if (mode == 0)      { Abase = g_emb + (size_t)by * 64 * EMBED;  lda = EMBED;  K = EMBED;
                          Cbase = g_U   + (size_t)by * 64 * HIDDEN; ldc = HIDDEN; }
    else if (mode == 1) { Abase = g_comb;                           lda = CDIM;   K = CDIM;
                          Cbase = Cext;                             ldc = OUTN; }
    else if (mode == 2) { Abase = g_Wt  + (size_t)by * 64 * HIDDEN; lda = HIDDEN; K = HIDDEN;
                          Cbase = g_W2t + (size_t)by * 64 * HIDDEN; ldc = HIDDEN; }
    else                { Abase = g_U + (size_t)(2 * by + 1) * 64 * HIDDEN; lda = HIDDEN; K = HIDDEN;
                          Cbase = g_V + (size_t)by * 64 * HIDDEN;           ldc = HIDDEN;
                          addbase = g_U + (size_t)(2 * by + 2) * 64 * HIDDEN; }

    const int sm_ = tid >> 2;            // staging row 0..63
    const int sk_ = (tid & 3) << 3;      // staging k offset {0,8,16,24}
    const float* Ag = Abase + (size_t)sm_ * lda + sk_;
    const float* Bg = Bw + (size_t)(n0 + sm_) * CDIM + sk_;

    unsigned long long acc[2][4] = {0ull, 0ull, 0ull, 0ull, 0ull, 0ull, 0ull, 0ull};

    for (int kb = 0; kb < K; kb += 32) {
        float4 av0 = *(const float4*)(Ag + kb);
        float4 av1 = *(const float4*)(Ag + kb + 4);
        float4 bv0 = *(const float4*)(Bg + kb);
        float4 bv1 = *(const float4*)(Bg + kb + 4);
        __syncthreads();
        As[(sk_ + 0) * 69 + sm_] = av0.x;  As[(sk_ + 1) * 69 + sm_] = av0.y;
        As[(sk_ + 2) * 69 + sm_] = av0.z;  As[(sk_ + 3) * 69 + sm_] = av0.w;
        As[(sk_ + 4) * 69 + sm_] = av1.x;  As[(sk_ + 5) * 69 + sm_] = av1.y;
        As[(sk_ + 6) * 69 + sm_] = av1.z;  As[(sk_ + 7) * 69 + sm_] = av1.w;
        Bs[(sk_ + 0) * 68 + sm_] = bv0.x;  Bs[(sk_ + 1) * 68 + sm_] = bv0.y;
        Bs[(sk_ + 2) * 68 + sm_] = bv0.z;  Bs[(sk_ + 3) * 68 + sm_] = bv0.w;
        Bs[(sk_ + 4) * 68 + sm_] = bv1.x;  Bs[(sk_ + 5) * 68 + sm_] = bv1.y;
        Bs[(sk_ + 6) * 68 + sm_] = bv1.z;  Bs[(sk_ + 7) * 68 + sm_] = bv1.w;
        __syncthreads();
#pragma unroll
        for (int kk = 0; kk < 32; ++kk) {
            float a0 = As[kk * 69 + l];
            float a1 = As[kk * 69 + l + 32];
            unsigned long long p0 = pk2(a0), p1 = pk2(a1);
            ulonglong2 wv0 = *(const ulonglong2*)(Bs + kk * 68 + (w << 3));
            ulonglong2 wv1 = *(const ulonglong2*)(Bs + kk * 68 + (w << 3) + 4);
            FMA2(acc[0][0], p0, wv0.x);  FMA2(acc[0][1], p0, wv0.y);
            FMA2(acc[0][2], p0, wv1.x);  FMA2(acc[0][3], p0, wv1.y);
            FMA2(acc[1][0], p1, wv0.x);  FMA2(acc[1][1], p1, wv0.y);
            FMA2(acc[1][2], p1, wv1.x);  FMA2(acc[1][3], p1, wv1.y);
        }
    }

#pragma unroll
    for (int r = 0; r < 2; ++r) {
        int m = l + (r << 5);
        int nb = n0 + (w << 3);
        float o[8];
#pragma unroll
        for (int p = 0; p < 4; ++p) { float2 v = upk(acc[r][p]); o[2 * p] = v.x; o[2 * p + 1] = v.y; }
        if (biasp) {
#pragma unroll
            for (int i = 0; i < 8; ++i) o[i] += biasp[nb + i];
        }
        if (addbase) {
            const float* ap = addbase + (size_t)m * HIDDEN + nb;
#pragma unroll
            for (int i = 0; i < 8; ++i) o[i] += ap[i];
        }
        float4* cp = (float4*)(Cbase + (size_t)m * ldc + nb);
        cp[0] = make_float4(o[0], o[1], o[2], o[3]);
        cp[1] = make_float4(o[4], o[5], o[6], o[7]);
    }
}

// ---------------- scan init: Z0 = h1 = U[0], Z1 = V[0], Z2 = 0 ----------------
__global__ void k_zinit() {
    int idx = blockIdx.x * blockDim.x + threadIdx.x;
    if (idx < BATCH * HIDDEN) {
        g_Z[0][idx] = g_U[idx];
        g_Z[1][idx] = g_V[idx];
        g_Z[2][idx] = 0.f;
    }
    if (idx == 0) g_bar = 0u;
}

// ---------------- persistent doubled scan: h' = h @ W2^T + V_s, 255 steps ----------------
// 128 CTAs = 16 jg (64 j) x 8 kg (128 k). Warp -> 8 j; lane -> b = {l, l+32}.
__global__ void __launch_bounds__(256) k_scan() {
    extern __shared__ float sm[];
    float* ws = sm;              // [128 k][68] (j contiguous, broadcast reads)
    float* hs = sm + 128 * 68;   // [64 b][132] (k contiguous, float4 reads)
    const int tid = threadIdx.x, bid = blockIdx.x;
    const int jg = bid >> 3, kg = bid & 7;
    const int j0 = jg << 6, k0 = kg << 7;
    const int w = tid >> 5, l = tid & 31;

    // weights once: ws[k][j] = W2t[k0+k][j0+j]
    for (int q = tid; q < 2048; q += 256) {
        int k = q >> 4, j4 = q & 15;
        float4 v = *(const float4*)(g_W2t + (size_t)(k0 + k) * HIDDEN + j0 + (j4 << 2));
        *(float4*)(ws + k * 68 + (j4 << 2)) = v;
    }

    unsigned target = 0;
    for (int t = 0; t < NHALF; ++t) {
        const float* Zr = g_Z[t % 3];
        float*       Zn = g_Z[(t + 1) % 3];
        float*       Zp = g_Z[(t + 2) % 3];

        for (int q = tid; q < 2048; q += 256) {
            int b = q >> 5, c4 = q & 31;
            float4 v = __ldcg((const float4*)(Zr + b * HIDDEN + k0 + (c4 << 2)));
            *(float4*)(hs + b * 132 + (c4 << 2)) = v;
        }
        __syncthreads();

        unsigned long long acc[2][4] = {0ull, 0ull, 0ull, 0ull, 0ull, 0ull, 0ull, 0ull};
        const float* h0p = hs + l * 132;
        const float* h1p = hs + (l + 32) * 132;
#pragma unroll 4
        for (int k4 = 0; k4 < 32; ++k4) {
            float4 a0 = *(const float4*)(h0p + (k4 << 2));
            float4 a1 = *(const float4*)(h1p + (k4 << 2));
            const float* wp = ws + (k4 << 2) * 68 + (w << 3);
            float a0v[4] = {a0.x, a0.y, a0.z, a0.w};
            float a1v[4] = {a1.x, a1.y, a1.z, a1.w};
#pragma unroll
            for (int i = 0; i < 4; ++i) {
                unsigned long long p0 = pk2(a0v[i]), p1 = pk2(a1v[i]);
                ulonglong2 wv0 = *(const ulonglong2*)(wp + i * 68);
                ulonglong2 wv1 = *(const ulonglong2*)(wp + i * 68 + 4);
                FMA2(acc[0][0], p0, wv0.x);  FMA2(acc[0][1], p0, wv0.y);
                FMA2(acc[0][2], p0, wv1.x);  FMA2(acc[0][3], p0, wv1.y);
                FMA2(acc[1][0], p1, wv0.x);  FMA2(acc[1][1], p1, wv0.y);
                FMA2(acc[1][2], p1, wv1.x);  FMA2(acc[1][3], p1, wv1.y);
            }
        }

#pragma unroll
        for (int r = 0; r < 2; ++r) {
            int b = l + (r << 5);
            float* zrow = Zn + b * HIDDEN + j0 + (w << 3);
#pragma unroll
            for (int p = 0; p < 4; ++p) {
                float2 v = upk(acc[r][p]);
                atomicAdd(zrow + 2 * p,     v.x);
                atomicAdd(zrow + 2 * p + 1, v.y);
            }
        }

        if (t < NHALF - 1) {
            float2 v = *(const float2*)(g_V + (size_t)(t + 1) * (BATCH * HIDDEN)
                                        + bid * 512 + tid * 2);
            *(float2*)(Zp + bid * 512 + tid * 2) = v;
        }

        target += NCTA;
        __threadfence();
        __syncthreads();
        if (tid == 0) {
            atomicAdd(&g_bar, 1u);
            while (*((volatile unsigned*)&g_bar) < target) { }
        }
        __syncthreads();
    }
}

// ---------------- combined = concat(emb[:, -1], h_last = Z[255%3] = Z[0]) ----------------
__global__ void k_combined() {
    int idx = blockIdx.x * blockDim.x + threadIdx.x;
    if (idx >= BATCH * CDIM) return;
    int b = idx / CDIM, c = idx - b * CDIM;
    float v;
    if (c < EMBED) v = g_emb[(size_t)(NSTEP * BATCH + b) * EMBED + c];  // t = 511
    else           v = g_Z[0][b * HIDDEN + (c - EMBED)];
    g_comb[idx] = v;
}

// ---------------- softmax ----------------
__device__ __forceinline__ float blk_reduce(float v, bool is_max) {
    __shared__ float red[32];
    int lane = threadIdx.x & 31, wid = threadIdx.x >> 5;
#pragma unroll
    for (int o = 16; o > 0; o >>= 1) {
        float u = __shfl_xor_sync(0xffffffffu, v, o);
        v = is_max ? fmaxf(v, u) : (v + u);
    }
    if (lane == 0) red[wid] = v;
    __syncthreads();
    v = (lane < 32) ? red[lane] : (is_max ? -3.0e38f : 0.f);
    if (wid == 0) {
#pragma unroll
        for (int o = 16; o > 0; o >>= 1) {
            float u = __shfl_xor_sync(0xffffffffu, v, o);
            v = is_max ? fmaxf(v, u) : (v + u);
        }
        if (lane == 0) red[0] = v;
    }
    __syncthreads();
    v = red[0];
    __syncthreads();
    return v;
}

__global__ void __launch_bounds__(1024) k_softmax(float* __restrict__ out) {
    float* row = out + (size_t)blockIdx.x * OUTN;
    int tid = threadIdx.x;
    float mx = -3.0e38f;
    for (int i = tid; i < OUTN; i += 1024) mx = fmaxf(mx, row[i]);
    mx = blk_reduce(mx, true);
    float s = 0.f;
    for (int i = tid; i < OUTN; i += 1024) {
        float e = expf(row[i] - mx);
        row[i] = e;
        s += e;
    }
    s = blk_reduce(s, false);
    float inv = 1.0f / s;
    for (int i = tid; i < OUTN; i += 1024) row[i] *= inv;
}

// ---------------- launch ----------------
extern "C" void kernel_launch(void* const* d_in, const int* in_sizes, int n_in,
                              void* d_out, int out_size) {
    const int*   tokens = (const int*)  d_in[0];
    const float* i2e_w  = (const float*)d_in[1];
    const float* i2e_b  = (const float*)d_in[2];
    const float* i2o_w  = (const float*)d_in[3];
    const float* i2o_b  = (const float*)d_in[4];
    const float* i2h_w  = (const float*)d_in[5];
    const float* i2h_b  = (const float*)d_in[6];
    float* out = (float*)d_out;

    cudaFuncSetAttribute(k_scan, cudaFuncAttributeMaxDynamicSharedMemorySize, 69632);

    k_transpose<<<dim3(VOCAB / 32, EMBED / 32), dim3(32, 8)>>>(i2e_w, i2e_b);
    k_gather<<<TLEN * BATCH, 128>>>(tokens);
    k_transposeW<<<dim3(32, 32), dim3(32, 8)>>>(i2h_w);
    // W2t = Wt @ W^T
    k_gemm2<<<dim3(16, 16), 256>>>(2, i2h_w + EMBED, nullptr, nullptr);
    // U[t] = emb[t] @ Wh_e^T + i2h_b   (t = 0..510)
    k_gemm2<<<dim3(16, NSTEP), 256>>>(0, i2h_w, i2h_b, nullptr);
    // V[s] = U[2s+1] @ W^T + U[2s+2]   (s = 0..254)
    k_gemm2<<<dim3(16, NHALF), 256>>>(3, i2h_w + EMBED, nullptr, nullptr);
    k_zinit<<<64, 1024>>>();
    k_scan<<<NCTA, 256, 69632>>>();
    k_combined<<<96, 1024>>>();
    // logits = comb @ i2o_w^T + i2o_b
    k_gemm2<<<dim3(OUTN / 64, 1), 256>>>(1, i2o_w, i2o_b, out);
    k_softmax<<<BATCH, 1024>>>(out);
}